// round 16
// baseline (speedup 1.0000x reference)
#include <cuda_runtime.h>
#include <cuda_fp16.h>
#include <math.h>
#include <stdint.h>

// ---------------------------------------------------------------------------
// Problem constants
// ---------------------------------------------------------------------------
#define BB   8
#define NN   1374
#define CC   768
#define HH   12
#define HD   64
#define C3   2304
#define HID  3072
#define MM   (BB * NN)          // 10992 rows
#define LN_EPS 1e-5f

// ---------------------------------------------------------------------------
// Scratch (device globals; no allocations allowed)
// ---------------------------------------------------------------------------
__device__ __half g_h[MM * CC];         // LN output (fp16)
__device__ __half g_qkv[MM * C3];       // QKV output (fp16, RoPE in place)
__device__ __half g_attn[MM * CC];      // attention output (fp16)
__device__ __half g_x1[MM * HID];       // MLP x1 (fp16)
__device__ __half g_hid[MM * HID];      // silu(x1)*x2 (fp16)
// fp16 weight copies (element offsets)
#define WH_QKV  0
#define WH_PROJ 1769472
#define WH_W1   2359296
#define WH_W2   4718592
#define WH_W3   7077888
#define WH_TOT  9437184
__device__ __half g_wh[WH_TOT];

// ---------------------------------------------------------------------------
// Helpers
// ---------------------------------------------------------------------------
__device__ __forceinline__ uint32_t smem_u32(const void* p) {
    uint32_t a;
    asm("{ .reg .u64 t; cvta.to.shared.u64 t, %1; cvt.u32.u64 %0, t; }"
        : "=r"(a) : "l"(p));
    return a;
}
__device__ __forceinline__ void cp_async16(uint32_t dst, const void* src, uint32_t sz) {
    asm volatile("cp.async.cg.shared.global [%0], [%1], 16, %2;"
                 :: "r"(dst), "l"(src), "r"(sz));
}
#define CP_COMMIT() asm volatile("cp.async.commit_group;" ::: "memory")
#define CP_WAIT1()  asm volatile("cp.async.wait_group 1;" ::: "memory")
#define CP_WAIT0()  asm volatile("cp.async.wait_group 0;" ::: "memory")

__device__ __forceinline__ void ldsm_x4(uint32_t* r, uint32_t addr) {
    asm volatile("ldmatrix.sync.aligned.m8n8.x4.shared.b16 {%0,%1,%2,%3}, [%4];"
        : "=r"(r[0]), "=r"(r[1]), "=r"(r[2]), "=r"(r[3]) : "r"(addr));
}
__device__ __forceinline__ void ldsm_x4_t(uint32_t* r, uint32_t addr) {
    asm volatile("ldmatrix.sync.aligned.m8n8.x4.trans.shared.b16 {%0,%1,%2,%3}, [%4];"
        : "=r"(r[0]), "=r"(r[1]), "=r"(r[2]), "=r"(r[3]) : "r"(addr));
}
__device__ __forceinline__ void mma_f16(float* d, const uint32_t* a, const uint32_t* b) {
    asm volatile(
        "mma.sync.aligned.m16n8k16.row.col.f32.f16.f16.f32 "
        "{%0,%1,%2,%3}, {%4,%5,%6,%7}, {%8,%9}, {%0,%1,%2,%3};"
        : "+f"(d[0]), "+f"(d[1]), "+f"(d[2]), "+f"(d[3])
        : "r"(a[0]), "r"(a[1]), "r"(a[2]), "r"(a[3]), "r"(b[0]), "r"(b[1]));
}

// ---------------------------------------------------------------------------
// fp32 -> fp16 conversion (weights)
// ---------------------------------------------------------------------------
__global__ void f2h_kernel(const float* __restrict__ in,
                           __half* __restrict__ out, int n4)
{
    int idx = blockIdx.x * blockDim.x + threadIdx.x;
    if (idx >= n4) return;
    float4 v = ((const float4*)in)[idx];
    ((__half2*)out)[idx * 2]     = __floats2half2_rn(v.x, v.y);
    ((__half2*)out)[idx * 2 + 1] = __floats2half2_rn(v.z, v.w);
}

// ---------------------------------------------------------------------------
// fp16 tensor-core NT GEMM. BM=BN=128, BK=64 halves, 8 warps (2m x 4n),
// warp tile 64x32. 3-stage cp.async pipeline, ldmatrix fragment loads.
// MODE 0: fp32+bias. 1: fp32+bias+residual(fp32). 2: fused SwiGLU (G fp16).
// MODE 3: fp16+bias.
// ---------------------------------------------------------------------------
#define HG_LD   72
#define HG_ASTF (128 * HG_LD)            // 9216 halves per operand stage
#define HG_STF  (2 * HG_ASTF)            // 18432 halves per stage
#define HG_SMEM (3 * HG_STF * 2)         // 110592 bytes

template <int MODE>
__global__ void __launch_bounds__(256, 2)
gemm_f16(const __half* __restrict__ A, const __half* __restrict__ W,
         const float* __restrict__ bias, const void* __restrict__ RG,
         void* __restrict__ outp, int M, int N, int K)
{
    extern __shared__ __half smh[];
    const uint32_t sb = smem_u32(smh);
    const int tid  = threadIdx.x;
    const int warp = tid >> 5;
    const int lane = tid & 31;
    const int wm = warp >> 2;            // 0..1 (m strip *64)
    const int wn = warp & 3;             // 0..3 (n strip *32)
    const int r = lane >> 2;
    const int c = lane & 3;
    const int m0 = blockIdx.y * 128;
    const int n0 = blockIdx.x * 128;

    // ldmatrix lane-address offsets (halves)
    const int a_row = wm * 64 + (lane & 15);
    const int a_col = (lane >> 4) << 3;
    const int b_row = wn * 32 + ((lane >> 4) << 3) + (lane & 7);
    const int b_col = ((lane >> 3) & 1) << 3;

    float acc[4][4][4];
    #pragma unroll
    for (int i = 0; i < 4; i++)
        #pragma unroll
        for (int j = 0; j < 4; j++)
            #pragma unroll
            for (int e = 0; e < 4; e++) acc[i][j][e] = 0.0f;

    const int nchunk = K >> 6;           // BK=64

    auto load_stage = [&](int s, int ch) {
        const int k0 = ch << 6;
        const uint32_t sa = sb + (uint32_t)(s * HG_STF) * 2u;
        // A: 128 rows x 64 halves = 1024 x 16B chunks
        #pragma unroll
        for (int i = 0; i < 4; i++) {
            int idx = tid + i * 256;
            int row = idx >> 3, c8 = idx & 7;
            int gm = m0 + row;
            int gms = gm < M ? gm : M - 1;
            const __half* src = A + (size_t)gms * K + k0 + c8 * 8;
            cp_async16(sa + (uint32_t)(row * HG_LD + c8 * 8) * 2u, src,
                       gm < M ? 16u : 0u);
        }
        // B: 128 rows x 64 halves
        #pragma unroll
        for (int i = 0; i < 4; i++) {
            int idx = tid + i * 256;
            int row = idx >> 3, c8 = idx & 7;
            const __half* src = W + (size_t)(n0 + row) * K + k0 + c8 * 8;
            cp_async16(sa + (uint32_t)(HG_ASTF + row * HG_LD + c8 * 8) * 2u,
                       src, 16u);
        }
    };

    load_stage(0, 0); CP_COMMIT();
    load_stage(1, 1); CP_COMMIT();

    for (int ch = 0; ch < nchunk; ch++) {
        int s = ch % 3;
        CP_WAIT1();
        __syncthreads();
        if (ch + 2 < nchunk) load_stage((ch + 2) % 3, ch + 2);
        CP_COMMIT();

        const uint32_t sa = sb + (uint32_t)(s * HG_STF) * 2u;
        const uint32_t a_lm = sa + (uint32_t)(a_row * HG_LD + a_col) * 2u;
        const uint32_t b_lm = sa + (uint32_t)((HG_ASTF) + b_row * HG_LD + b_col) * 2u;

        #pragma unroll
        for (int ks = 0; ks < 4; ks++) {            // 4 k16 steps
            uint32_t af[4][4], bf[2][4];
            #pragma unroll
            for (int i = 0; i < 4; i++)
                ldsm_x4(af[i], a_lm + (uint32_t)(i * 16 * HG_LD + ks * 16) * 2u);
            #pragma unroll
            for (int jj = 0; jj < 2; jj++)
                ldsm_x4(bf[jj], b_lm + (uint32_t)(jj * 16 * HG_LD + ks * 16) * 2u);
            #pragma unroll
            for (int i = 0; i < 4; i++) {
                #pragma unroll
                for (int jj = 0; jj < 2; jj++) {
                    mma_f16(acc[i][jj * 2 + 0], af[i], &bf[jj][0]);
                    mma_f16(acc[i][jj * 2 + 1], af[i], &bf[jj][2]);
                }
            }
        }
    }

    // epilogue
    #pragma unroll
    for (int i = 0; i < 4; i++) {
        int gr0 = m0 + wm * 64 + i * 16 + r;
        #pragma unroll
        for (int half_m = 0; half_m < 2; half_m++) {
            int gm = gr0 + half_m * 8;
            if (gm >= M) continue;
            #pragma unroll
            for (int j = 0; j < 4; j++) {
                int gn = n0 + wn * 32 + j * 8 + 2 * c;
                float2 b2 = *(const float2*)&bias[gn];
                float vx = acc[i][j][half_m * 2 + 0] + b2.x;
                float vy = acc[i][j][half_m * 2 + 1] + b2.y;
                if (MODE == 0) {
                    float2 o; o.x = vx; o.y = vy;
                    *(float2*)&((float*)outp)[(size_t)gm * N + gn] = o;
                } else if (MODE == 1) {
                    float2 r2 = *(const float2*)&((const float*)RG)[(size_t)gm * N + gn];
                    float2 o; o.x = vx + r2.x; o.y = vy + r2.y;
                    *(float2*)&((float*)outp)[(size_t)gm * N + gn] = o;
                } else if (MODE == 2) {
                    __half2 g2h = *(const __half2*)&((const __half*)RG)[(size_t)gm * N + gn];
                    float2 g2 = __half22float2(g2h);
                    float sx = g2.x / (1.0f + __expf(-g2.x));
                    float sy = g2.y / (1.0f + __expf(-g2.y));
                    *(__half2*)&((__half*)outp)[(size_t)gm * N + gn] =
                        __floats2half2_rn(sx * vx, sy * vy);
                } else {
                    *(__half2*)&((__half*)outp)[(size_t)gm * N + gn] =
                        __floats2half2_rn(vx, vy);
                }
            }
        }
    }
}

// ---------------------------------------------------------------------------
// LayerNorm: one block per row of 768. fp16 output.
// ---------------------------------------------------------------------------
__global__ void ln_kernel(const float* __restrict__ x,
                          const float* __restrict__ g,
                          const float* __restrict__ b,
                          __half* __restrict__ out)
{
    int row = blockIdx.x;
    int tid = threadIdx.x;
    int lane = tid & 31;
    int wid  = tid >> 5;
    const float* xr = x + (size_t)row * CC;

    float v0 = xr[tid];
    float v1 = xr[tid + 256];
    float v2 = xr[tid + 512];

    __shared__ float red[8];

    float s = v0 + v1 + v2;
    #pragma unroll
    for (int off = 16; off > 0; off >>= 1) s += __shfl_xor_sync(0xffffffffu, s, off);
    if (lane == 0) red[wid] = s;
    __syncthreads();
    float tot = red[0] + red[1] + red[2] + red[3] + red[4] + red[5] + red[6] + red[7];
    float mean = tot * (1.0f / (float)CC);
    __syncthreads();

    float d0 = v0 - mean, d1 = v1 - mean, d2 = v2 - mean;
    float sq = d0 * d0 + d1 * d1 + d2 * d2;
    #pragma unroll
    for (int off = 16; off > 0; off >>= 1) sq += __shfl_xor_sync(0xffffffffu, sq, off);
    if (lane == 0) red[wid] = sq;
    __syncthreads();
    float tot2 = red[0] + red[1] + red[2] + red[3] + red[4] + red[5] + red[6] + red[7];
    float var = tot2 * (1.0f / (float)CC);
    float rstd = rsqrtf(var + LN_EPS);

    __half* orow = out + (size_t)row * CC;
    orow[tid]       = __float2half(d0 * rstd * g[tid]       + b[tid]);
    orow[tid + 256] = __float2half(d1 * rstd * g[tid + 256] + b[tid + 256]);
    orow[tid + 512] = __float2half(d2 * rstd * g[tid + 512] + b[tid + 512]);
}

// ---------------------------------------------------------------------------
// RoPE in place on fp16 qkv. One block per token row; fast sincos.
// ---------------------------------------------------------------------------
__global__ void rope_kernel(__half* __restrict__ qkv,
                            const float* __restrict__ freqs)
{
    const int m = blockIdx.x;
    const int n = m % NN;
    const size_t mbase = (size_t)m * C3;
    for (int e = threadIdx.x; e < 768; e += 256) {
        int s  = e >= 384;
        int hr = e - s * 384;
        int h  = hr >> 5;
        int dd = hr & 31;
        size_t base = mbase + s * CC + h * HD;
        float f1 = freqs[n * HD + dd];
        float f2 = freqs[n * HD + dd + 32];
        float s1, c1, s2, c2;
        __sincosf(f1, &s1, &c1);
        __sincosf(f2, &s2, &c2);
        float x1 = __half2float(qkv[base + dd]);
        float x2 = __half2float(qkv[base + dd + 32]);
        qkv[base + dd]      = __float2half(x1 * c1 - x2 * s1);
        qkv[base + dd + 32] = __float2half(x2 * c2 + x1 * s2);
    }
}

// ---------------------------------------------------------------------------
// fp16 flash attention. BQ=128, BKV=64, 8 warps; warp w owns q-strip w*16.
// All tiles loaded via cp.async (zero-fill OOB); fragments via ldmatrix;
// V kept row-major [kv][d], PV B-fragments via ldmatrix.trans.
// ---------------------------------------------------------------------------
#define FH_LD 72
#define FS_LD 68
#define FA_SMEM ((128 * FS_LD + 3 * 128) * 4 + \
                 (128 * FH_LD + 64 * FH_LD + 64 * FH_LD + 128 * FH_LD) * 2) // 91648

__global__ void __launch_bounds__(256)
flash_f16_kernel(const __half* __restrict__ qkv, __half* __restrict__ o)
{
    extern __shared__ char fsm[];
    float*  Ss    = (float*)fsm;                 // [128][FS_LD] fp32
    float*  row_m = Ss + 128 * FS_LD;
    float*  row_l = row_m + 128;
    float*  row_s = row_l + 128;
    __half* Qs    = (__half*)(row_s + 128);      // [128][FH_LD]
    __half* Ks    = Qs + 128 * FH_LD;            // [64][FH_LD]
    __half* Vs    = Ks + 64 * FH_LD;             // [64][FH_LD] row-major (kv, d)
    __half* Ps    = Vs + 64 * FH_LD;             // [128][FH_LD] fp16

    const uint32_t sbq = smem_u32(Qs);
    const uint32_t sbk = smem_u32(Ks);
    const uint32_t sbv = smem_u32(Vs);
    const uint32_t sbp = smem_u32(Ps);
    const int tid  = threadIdx.x;
    const int warp = tid >> 5;
    const int lane = tid & 31;
    const int fr = lane >> 2;
    const int fc = lane & 3;
    const int q0 = blockIdx.x * 128;
    const int b  = blockIdx.y / HH;
    const int h  = blockIdx.y % HH;
    const size_t headoff = (size_t)h * HD;

    // ldmatrix lane offsets
    const int lm_row = lane & 15;
    const int lm_hi8 = (lane >> 4) << 3;
    const int kb_row = ((lane >> 4) << 3) + (lane & 7);   // B non-trans row
    const int kb_col = ((lane >> 3) & 1) << 3;            // B non-trans k-col

    if (tid < 128) { row_m[tid] = -INFINITY; row_l[tid] = 0.0f; }

    // Q tile: cp.async fp16 copy (128 rows x 8 x 16B)
    #pragma unroll
    for (int i = 0; i < 4; i++) {
        int idx = tid + i * 256;
        int r = idx >> 3, c8 = idx & 7;
        int n = q0 + r;
        int ns = n < NN ? n : NN - 1;
        const __half* src = qkv + (size_t)(b * NN + ns) * C3 + headoff + c8 * 8;
        cp_async16(sbq + (uint32_t)(r * FH_LD + c8 * 8) * 2u, src, n < NN ? 16u : 0u);
    }
    CP_COMMIT();

    float oacc[8][4];
    #pragma unroll
    for (int j = 0; j < 8; j++)
        #pragma unroll
        for (int e = 0; e < 4; e++) oacc[j][e] = 0.0f;

    const int ntiles = (NN + 63) / 64;   // 22

    for (int t = 0; t < ntiles; t++) {
        const int kv0 = t * 64;
        __syncthreads();                 // previous Ks/Vs/Ps readers done

        // K + V tiles via cp.async (64 rows x 8 x 16B each)
        #pragma unroll
        for (int i = 0; i < 2; i++) {
            int idx = tid + i * 256;
            int r = idx >> 3, c8 = idx & 7;
            int n = kv0 + r;
            int ns = n < NN ? n : NN - 1;
            size_t base = (size_t)(b * NN + ns) * C3 + headoff + c8 * 8;
            uint32_t valid = n < NN ? 16u : 0u;
            cp_async16(sbk + (uint32_t)(r * FH_LD + c8 * 8) * 2u,
                       qkv + base + CC, valid);
            cp_async16(sbv + (uint32_t)(r * FH_LD + c8 * 8) * 2u,
                       qkv + base + 2 * CC, valid);
        }
        CP_COMMIT();
        CP_WAIT0();
        __syncthreads();

        // S = Q @ K^T : warp tile 16(q) x 64(kv); 4 k16 steps over d
        float sacc[8][4];
        #pragma unroll
        for (int j = 0; j < 8; j++)
            #pragma unroll
            for (int e = 0; e < 4; e++) sacc[j][e] = 0.0f;
        {
            const uint32_t q_lm = sbq +
                (uint32_t)((warp * 16 + lm_row) * FH_LD + lm_hi8) * 2u;
            const uint32_t k_lm = sbk +
                (uint32_t)(kb_row * FH_LD + kb_col) * 2u;
            #pragma unroll
            for (int ks = 0; ks < 4; ks++) {
                uint32_t af[4];
                ldsm_x4(af, q_lm + (uint32_t)(ks * 16) * 2u);
                #pragma unroll
                for (int jj = 0; jj < 4; jj++) {
                    uint32_t bf[4];
                    ldsm_x4(bf, k_lm + (uint32_t)(jj * 16 * FH_LD + ks * 16) * 2u);
                    mma_f16(sacc[jj * 2 + 0], af, &bf[0]);
                    mma_f16(sacc[jj * 2 + 1], af, &bf[2]);
                }
            }
        }
        // write S (fp32)
        #pragma unroll
        for (int j = 0; j < 8; j++) {
            float* d0 = Ss + (warp * 16 + fr) * FS_LD + j * 8 + 2 * fc;
            d0[0] = sacc[j][0]; d0[1] = sacc[j][1];
            float* d1 = d0 + 8 * FS_LD;
            d1[0] = sacc[j][2]; d1[1] = sacc[j][3];
        }
        __syncthreads();

        // online softmax over 128 rows (two 64-row halves); scale here
        #pragma unroll
        for (int half = 0; half < 2; half++) {
            int r = (tid >> 2) + half * 64;
            int part = tid & 3;
            float pv[16];
            #pragma unroll
            for (int j4 = 0; j4 < 4; j4++) {
                float4 v4 = *(const float4*)&Ss[r * FS_LD + part * 16 + j4 * 4];
                pv[j4*4+0] = v4.x * 0.125f; pv[j4*4+1] = v4.y * 0.125f;
                pv[j4*4+2] = v4.z * 0.125f; pv[j4*4+3] = v4.w * 0.125f;
            }
            if (kv0 + 64 > NN) {
                #pragma unroll
                for (int j = 0; j < 16; j++)
                    if (kv0 + part * 16 + j >= NN) pv[j] = -INFINITY;
            }
            float lmax = pv[0];
            #pragma unroll
            for (int j = 1; j < 16; j++) lmax = fmaxf(lmax, pv[j]);
            lmax = fmaxf(lmax, __shfl_xor_sync(0xffffffffu, lmax, 1));
            lmax = fmaxf(lmax, __shfl_xor_sync(0xffffffffu, lmax, 2));
            float m_old = row_m[r];
            float m_new = fmaxf(m_old, lmax);
            float lsum = 0.0f;
            #pragma unroll
            for (int j = 0; j < 16; j++) {
                pv[j] = __expf(pv[j] - m_new);
                lsum += pv[j];
            }
            lsum += __shfl_xor_sync(0xffffffffu, lsum, 1);
            lsum += __shfl_xor_sync(0xffffffffu, lsum, 2);
            float sc = __expf(m_old - m_new);
            if (part == 0) {
                row_s[r] = sc;
                row_m[r] = m_new;
                row_l[r] = row_l[r] * sc + lsum;
            }
            #pragma unroll
            for (int j4 = 0; j4 < 4; j4++) {
                *(__half2*)&Ps[r * FH_LD + part * 16 + j4 * 4] =
                    __floats2half2_rn(pv[j4 * 4 + 0], pv[j4 * 4 + 1]);
                *(__half2*)&Ps[r * FH_LD + part * 16 + j4 * 4 + 2] =
                    __floats2half2_rn(pv[j4 * 4 + 2], pv[j4 * 4 + 3]);
            }
        }
        __syncthreads();

        // rescale O and accumulate P @ V : A=P (ldmatrix), B=V (ldmatrix.trans)
        {
            float rs0 = row_s[warp * 16 + fr];
            float rs1 = row_s[warp * 16 + fr + 8];
            #pragma unroll
            for (int j = 0; j < 8; j++) {
                oacc[j][0] *= rs0; oacc[j][1] *= rs0;
                oacc[j][2] *= rs1; oacc[j][3] *= rs1;
            }
            const uint32_t p_lm = sbp +
                (uint32_t)((warp * 16 + lm_row) * FH_LD + lm_hi8) * 2u;
            const uint32_t v_lm = sbv +
                (uint32_t)(lm_row * FH_LD + lm_hi8) * 2u;
            #pragma unroll
            for (int ks = 0; ks < 4; ks++) {
                uint32_t af[4];
                ldsm_x4(af, p_lm + (uint32_t)(ks * 16) * 2u);
                #pragma unroll
                for (int jj = 0; jj < 4; jj++) {
                    uint32_t bf[4];
                    ldsm_x4_t(bf, v_lm + (uint32_t)(ks * 16 * FH_LD + jj * 16) * 2u);
                    mma_f16(oacc[jj * 2 + 0], af, &bf[0]);
                    mma_f16(oacc[jj * 2 + 1], af, &bf[2]);
                }
            }
        }
    }

    // normalize + store fp16
    {
        int r0 = warp * 16 + fr;
        float inv0 = 1.0f / row_l[r0];
        float inv1 = 1.0f / row_l[r0 + 8];
        int n0g = q0 + r0;
        int n1g = n0g + 8;
        #pragma unroll
        for (int j = 0; j < 8; j++) {
            size_t col = headoff + j * 8 + 2 * fc;
            if (n0g < NN) {
                *(__half2*)&o[(size_t)(b * NN + n0g) * CC + col] =
                    __floats2half2_rn(oacc[j][0] * inv0, oacc[j][1] * inv0);
            }
            if (n1g < NN) {
                *(__half2*)&o[(size_t)(b * NN + n1g) * CC + col] =
                    __floats2half2_rn(oacc[j][2] * inv1, oacc[j][3] * inv1);
            }
        }
    }
}

// ---------------------------------------------------------------------------
// Launch
// ---------------------------------------------------------------------------
static inline void conv_h(const float* in, __half* out, int elems) {
    int n4 = elems / 4;
    f2h_kernel<<<(n4 + 255) / 256, 256>>>(in, out, n4);
}

extern "C" void kernel_launch(void* const* d_in, const int* in_sizes, int n_in,
                              void* d_out, int out_size)
{
    const float* x      = (const float*)d_in[0];
    const float* freqs  = (const float*)d_in[1];
    const float* ln1_g  = (const float*)d_in[2];
    const float* ln1_b  = (const float*)d_in[3];
    const float* qkv_w  = (const float*)d_in[4];
    const float* qkv_b  = (const float*)d_in[5];
    const float* proj_w = (const float*)d_in[6];
    const float* proj_b = (const float*)d_in[7];
    const float* ln2_g  = (const float*)d_in[8];
    const float* ln2_b  = (const float*)d_in[9];
    const float* w1     = (const float*)d_in[10];
    const float* b1     = (const float*)d_in[11];
    const float* w2     = (const float*)d_in[12];
    const float* b2     = (const float*)d_in[13];
    const float* w3     = (const float*)d_in[14];
    const float* b3     = (const float*)d_in[15];
    float* out = (float*)d_out;

    __half *h_buf, *qkv_buf, *attn_buf, *x1_buf, *hid_buf, *wh;
    cudaGetSymbolAddress((void**)&h_buf, g_h);
    cudaGetSymbolAddress((void**)&qkv_buf, g_qkv);
    cudaGetSymbolAddress((void**)&attn_buf, g_attn);
    cudaGetSymbolAddress((void**)&x1_buf, g_x1);
    cudaGetSymbolAddress((void**)&hid_buf, g_hid);
    cudaGetSymbolAddress((void**)&wh, g_wh);

    cudaFuncSetAttribute(gemm_f16<0>,
                         cudaFuncAttributeMaxDynamicSharedMemorySize, HG_SMEM);
    cudaFuncSetAttribute(gemm_f16<1>,
                         cudaFuncAttributeMaxDynamicSharedMemorySize, HG_SMEM);
    cudaFuncSetAttribute(gemm_f16<2>,
                         cudaFuncAttributeMaxDynamicSharedMemorySize, HG_SMEM);
    cudaFuncSetAttribute(gemm_f16<3>,
                         cudaFuncAttributeMaxDynamicSharedMemorySize, HG_SMEM);
    cudaFuncSetAttribute(flash_f16_kernel,
                         cudaFuncAttributeMaxDynamicSharedMemorySize, FA_SMEM);

    const int mblocks = (MM + 127) / 128;   // 86

    // 0) weights -> fp16
    conv_h(qkv_w,  wh + WH_QKV,  C3 * CC);
    conv_h(proj_w, wh + WH_PROJ, CC * CC);
    conv_h(w1,     wh + WH_W1,   HID * CC);
    conv_h(w2,     wh + WH_W2,   HID * CC);
    conv_h(w3,     wh + WH_W3,   CC * HID);

    // 1) LN1 -> fp16
    ln_kernel<<<MM, 256>>>(x, ln1_g, ln1_b, h_buf);

    // 2) QKV GEMM -> fp16
    gemm_f16<3><<<dim3(C3 / 128, mblocks), 256, HG_SMEM>>>(
        h_buf, wh + WH_QKV, qkv_b, nullptr, qkv_buf, MM, C3, CC);

    // 3) RoPE in place (fp16)
    rope_kernel<<<MM, 256>>>(qkv_buf, freqs);

    // 4) Flash attention (BQ=128) -> fp16
    {
        dim3 grid((NN + 127) / 128, BB * HH);   // (11, 96)
        flash_f16_kernel<<<grid, 256, FA_SMEM>>>(qkv_buf, attn_buf);
    }

    // 5) proj GEMM + residual(x) -> out (fp32)
    gemm_f16<1><<<dim3(CC / 128, mblocks), 256, HG_SMEM>>>(
        attn_buf, wh + WH_PROJ, proj_b, x, out, MM, CC, CC);

    // 6) LN2 -> fp16
    ln_kernel<<<MM, 256>>>(out, ln2_g, ln2_b, h_buf);

    // 7) x1 GEMM -> fp16
    gemm_f16<3><<<dim3(HID / 128, mblocks), 256, HG_SMEM>>>(
        h_buf, wh + WH_W1, b1, nullptr, x1_buf, MM, HID, CC);

    // 8) x2 GEMM with fused SwiGLU (reads fp16 x1) -> hid (fp16)
    gemm_f16<2><<<dim3(HID / 128, mblocks), 256, HG_SMEM>>>(
        h_buf, wh + WH_W2, b2, x1_buf, hid_buf, MM, HID, CC);

    // 9) mlp GEMM + residual -> out (fp32)
    gemm_f16<1><<<dim3(CC / 128, mblocks), 256, HG_SMEM>>>(
        hid_buf, wh + WH_W3, b3, out, out, MM, CC, HID);
}

// round 17
// speedup vs baseline: 1.3322x; 1.3322x over previous
#include <cuda_runtime.h>
#include <cuda_fp16.h>
#include <math.h>
#include <stdint.h>

// ---------------------------------------------------------------------------
// Problem constants
// ---------------------------------------------------------------------------
#define BB   8
#define NN   1374
#define CC   768
#define HH   12
#define HD   64
#define C3   2304
#define HID  3072
#define MM   (BB * NN)          // 10992 rows
#define LN_EPS 1e-5f

// ---------------------------------------------------------------------------
// Scratch (device globals; no allocations allowed)
// ---------------------------------------------------------------------------
__device__ __half g_h[MM * CC];         // LN output (fp16)
__device__ __half g_qkv[MM * C3];       // QKV output (fp16, RoPE in place)
__device__ __half g_attn[MM * CC];      // attention output (fp16)
__device__ __half g_x1[MM * HID];       // MLP x1 (fp16)
__device__ __half g_hid[MM * HID];      // silu(x1)*x2 (fp16)
// fp16 weight copies (element offsets)
#define WH_QKV  0
#define WH_PROJ 1769472
#define WH_W1   2359296
#define WH_W2   4718592
#define WH_W3   7077888
#define WH_TOT  9437184
__device__ __half g_wh[WH_TOT];

// ---------------------------------------------------------------------------
// Helpers
// ---------------------------------------------------------------------------
__device__ __forceinline__ uint32_t smem_u32(const void* p) {
    uint32_t a;
    asm("{ .reg .u64 t; cvta.to.shared.u64 t, %1; cvt.u32.u64 %0, t; }"
        : "=r"(a) : "l"(p));
    return a;
}
__device__ __forceinline__ void cp_async16(uint32_t dst, const void* src, uint32_t sz) {
    asm volatile("cp.async.cg.shared.global [%0], [%1], 16, %2;"
                 :: "r"(dst), "l"(src), "r"(sz));
}
#define CP_COMMIT() asm volatile("cp.async.commit_group;" ::: "memory")
#define CP_WAIT1()  asm volatile("cp.async.wait_group 1;" ::: "memory")
#define CP_WAIT0()  asm volatile("cp.async.wait_group 0;" ::: "memory")

__device__ __forceinline__ uint32_t ldh2(const __half* p) {
    return *(const uint32_t*)p;          // aligned half2 load
}
__device__ __forceinline__ void ldsm_x4(uint32_t* r, uint32_t addr) {
    asm volatile("ldmatrix.sync.aligned.m8n8.x4.shared.b16 {%0,%1,%2,%3}, [%4];"
        : "=r"(r[0]), "=r"(r[1]), "=r"(r[2]), "=r"(r[3]) : "r"(addr));
}
__device__ __forceinline__ void mma_f16(float* d, const uint32_t* a, const uint32_t* b) {
    asm volatile(
        "mma.sync.aligned.m16n8k16.row.col.f32.f16.f16.f32 "
        "{%0,%1,%2,%3}, {%4,%5,%6,%7}, {%8,%9}, {%0,%1,%2,%3};"
        : "+f"(d[0]), "+f"(d[1]), "+f"(d[2]), "+f"(d[3])
        : "r"(a[0]), "r"(a[1]), "r"(a[2]), "r"(a[3]), "r"(b[0]), "r"(b[1]));
}

// ---------------------------------------------------------------------------
// fp32 -> fp16 conversion (weights)
// ---------------------------------------------------------------------------
__global__ void f2h_kernel(const float* __restrict__ in,
                           __half* __restrict__ out, int n4)
{
    int idx = blockIdx.x * blockDim.x + threadIdx.x;
    if (idx >= n4) return;
    float4 v = ((const float4*)in)[idx];
    ((__half2*)out)[idx * 2]     = __floats2half2_rn(v.x, v.y);
    ((__half2*)out)[idx * 2 + 1] = __floats2half2_rn(v.z, v.w);
}

// ---------------------------------------------------------------------------
// fp16 tensor-core NT GEMM. BM=BN=128, BK=32 halves, 8 warps (2m x 4n),
// warp tile 64x32. 3-stage cp.async pipeline (61 KB smem, 2 CTAs/SM).
// Fragment loads via ldmatrix.x4 within the LD=40 layout (R17 change).
// MODE 0: fp32+bias. 1: fp32+bias+residual(fp32). 2: fused SwiGLU (G fp16).
// MODE 3: fp16+bias.
// ---------------------------------------------------------------------------
#define HG_LD   40
#define HG_ASTF (128 * HG_LD)
#define HG_STF  (2 * HG_ASTF)
#define HG_SMEM (3 * HG_STF * 2)         // 61440 bytes

template <int MODE>
__global__ void __launch_bounds__(256, 2)
gemm_f16(const __half* __restrict__ A, const __half* __restrict__ W,
         const float* __restrict__ bias, const void* __restrict__ RG,
         void* __restrict__ outp, int M, int N, int K)
{
    extern __shared__ __half smh[];
    const uint32_t sb = smem_u32(smh);
    const int tid  = threadIdx.x;
    const int warp = tid >> 5;
    const int lane = tid & 31;
    const int wm = warp >> 2;            // 0..1 (m strip *64)
    const int wn = warp & 3;             // 0..3 (n strip *32)
    const int r = lane >> 2;
    const int c = lane & 3;
    const int m0 = blockIdx.y * 128;
    const int n0 = blockIdx.x * 128;

    // ldmatrix lane-address components (elements)
    const int a_row = wm * 64 + (lane & 15);
    const int a_col = (lane >> 4) << 3;                       // 0 / 8
    const int b_row = wn * 32 + ((lane >> 4) << 3) + (lane & 7);
    const int b_col = ((lane >> 3) & 1) << 3;                 // 0 / 8

    float acc[4][4][4];
    #pragma unroll
    for (int i = 0; i < 4; i++)
        #pragma unroll
        for (int j = 0; j < 4; j++)
            #pragma unroll
            for (int e = 0; e < 4; e++) acc[i][j][e] = 0.0f;

    const int nchunk = K >> 5;           // BK=32

    auto load_stage = [&](int s, int ch) {
        const int k0 = ch << 5;
        const uint32_t sa = sb + (uint32_t)(s * HG_STF) * 2u;
        #pragma unroll
        for (int i = 0; i < 2; i++) {
            int idx = tid + i * 256;
            int row = idx >> 2, ch16 = idx & 3;
            int gm = m0 + row;
            int gms = gm < M ? gm : M - 1;
            const __half* src = A + (size_t)gms * K + k0 + ch16 * 8;
            uint32_t dst = sa + (uint32_t)(row * HG_LD + ch16 * 8) * 2u;
            cp_async16(dst, src, gm < M ? 16u : 0u);
        }
        #pragma unroll
        for (int i = 0; i < 2; i++) {
            int idx = tid + i * 256;
            int row = idx >> 2, ch16 = idx & 3;
            const __half* src = W + (size_t)(n0 + row) * K + k0 + ch16 * 8;
            uint32_t dst = sa + (uint32_t)(HG_ASTF + row * HG_LD + ch16 * 8) * 2u;
            cp_async16(dst, src, 16u);
        }
    };

    load_stage(0, 0); CP_COMMIT();
    load_stage(1, 1); CP_COMMIT();

    for (int ch = 0; ch < nchunk; ch++) {
        int s = ch % 3;
        CP_WAIT1();
        __syncthreads();
        if (ch + 2 < nchunk) load_stage((ch + 2) % 3, ch + 2);
        CP_COMMIT();

        const uint32_t sa = sb + (uint32_t)(s * HG_STF) * 2u;
        const uint32_t a_lm = sa + (uint32_t)(a_row * HG_LD + a_col) * 2u;
        const uint32_t b_lm = sa + (uint32_t)(HG_ASTF + b_row * HG_LD + b_col) * 2u;

        #pragma unroll
        for (int ks = 0; ks < 2; ks++) {            // two k16 steps
            uint32_t af[4][4], bf[2][4];
            #pragma unroll
            for (int i = 0; i < 4; i++)
                ldsm_x4(af[i], a_lm + (uint32_t)(i * 16 * HG_LD + ks * 16) * 2u);
            #pragma unroll
            for (int jj = 0; jj < 2; jj++)
                ldsm_x4(bf[jj], b_lm + (uint32_t)(jj * 16 * HG_LD + ks * 16) * 2u);
            #pragma unroll
            for (int i = 0; i < 4; i++) {
                #pragma unroll
                for (int jj = 0; jj < 2; jj++) {
                    mma_f16(acc[i][jj * 2 + 0], af[i], &bf[jj][0]);
                    mma_f16(acc[i][jj * 2 + 1], af[i], &bf[jj][2]);
                }
            }
        }
    }

    // epilogue
    #pragma unroll
    for (int i = 0; i < 4; i++) {
        int gr0 = m0 + wm * 64 + i * 16 + r;
        #pragma unroll
        for (int half_m = 0; half_m < 2; half_m++) {
            int gm = gr0 + half_m * 8;
            if (gm >= M) continue;
            #pragma unroll
            for (int j = 0; j < 4; j++) {
                int gn = n0 + wn * 32 + j * 8 + 2 * c;
                float2 b2 = *(const float2*)&bias[gn];
                float vx = acc[i][j][half_m * 2 + 0] + b2.x;
                float vy = acc[i][j][half_m * 2 + 1] + b2.y;
                if (MODE == 0) {
                    float2 o; o.x = vx; o.y = vy;
                    *(float2*)&((float*)outp)[(size_t)gm * N + gn] = o;
                } else if (MODE == 1) {
                    float2 r2 = *(const float2*)&((const float*)RG)[(size_t)gm * N + gn];
                    float2 o; o.x = vx + r2.x; o.y = vy + r2.y;
                    *(float2*)&((float*)outp)[(size_t)gm * N + gn] = o;
                } else if (MODE == 2) {
                    __half2 g2h = *(const __half2*)&((const __half*)RG)[(size_t)gm * N + gn];
                    float2 g2 = __half22float2(g2h);
                    float sx = g2.x / (1.0f + __expf(-g2.x));
                    float sy = g2.y / (1.0f + __expf(-g2.y));
                    *(__half2*)&((__half*)outp)[(size_t)gm * N + gn] =
                        __floats2half2_rn(sx * vx, sy * vy);
                } else {
                    *(__half2*)&((__half*)outp)[(size_t)gm * N + gn] =
                        __floats2half2_rn(vx, vy);
                }
            }
        }
    }
}

// ---------------------------------------------------------------------------
// LayerNorm: one block per row of 768. fp16 output.
// ---------------------------------------------------------------------------
__global__ void ln_kernel(const float* __restrict__ x,
                          const float* __restrict__ g,
                          const float* __restrict__ b,
                          __half* __restrict__ out)
{
    int row = blockIdx.x;
    int tid = threadIdx.x;
    int lane = tid & 31;
    int wid  = tid >> 5;
    const float* xr = x + (size_t)row * CC;

    float v0 = xr[tid];
    float v1 = xr[tid + 256];
    float v2 = xr[tid + 512];

    __shared__ float red[8];

    float s = v0 + v1 + v2;
    #pragma unroll
    for (int off = 16; off > 0; off >>= 1) s += __shfl_xor_sync(0xffffffffu, s, off);
    if (lane == 0) red[wid] = s;
    __syncthreads();
    float tot = red[0] + red[1] + red[2] + red[3] + red[4] + red[5] + red[6] + red[7];
    float mean = tot * (1.0f / (float)CC);
    __syncthreads();

    float d0 = v0 - mean, d1 = v1 - mean, d2 = v2 - mean;
    float sq = d0 * d0 + d1 * d1 + d2 * d2;
    #pragma unroll
    for (int off = 16; off > 0; off >>= 1) sq += __shfl_xor_sync(0xffffffffu, sq, off);
    if (lane == 0) red[wid] = sq;
    __syncthreads();
    float tot2 = red[0] + red[1] + red[2] + red[3] + red[4] + red[5] + red[6] + red[7];
    float var = tot2 * (1.0f / (float)CC);
    float rstd = rsqrtf(var + LN_EPS);

    __half* orow = out + (size_t)row * CC;
    orow[tid]       = __float2half(d0 * rstd * g[tid]       + b[tid]);
    orow[tid + 256] = __float2half(d1 * rstd * g[tid + 256] + b[tid + 256]);
    orow[tid + 512] = __float2half(d2 * rstd * g[tid + 512] + b[tid + 512]);
}

// ---------------------------------------------------------------------------
// RoPE in place on fp16 qkv. One block per token row; fast sincos.
// ---------------------------------------------------------------------------
__global__ void rope_kernel(__half* __restrict__ qkv,
                            const float* __restrict__ freqs)
{
    const int m = blockIdx.x;
    const int n = m % NN;
    const size_t mbase = (size_t)m * C3;
    for (int e = threadIdx.x; e < 768; e += 256) {
        int s  = e >= 384;
        int hr = e - s * 384;
        int h  = hr >> 5;
        int dd = hr & 31;
        size_t base = mbase + s * CC + h * HD;
        float f1 = freqs[n * HD + dd];
        float f2 = freqs[n * HD + dd + 32];
        float s1, c1, s2, c2;
        __sincosf(f1, &s1, &c1);
        __sincosf(f2, &s2, &c2);
        float x1 = __half2float(qkv[base + dd]);
        float x2 = __half2float(qkv[base + dd + 32]);
        qkv[base + dd]      = __float2half(x1 * c1 - x2 * s1);
        qkv[base + dd + 32] = __float2half(x2 * c2 + x1 * s2);
    }
}

// ---------------------------------------------------------------------------
// fp16 flash attention (R14-exact). BQ=128, BKV=64, 8 warps; warp w owns
// q-strip w*16. mma m16n8k16. Q/K via cp.async; V transposed manually.
// Scale 0.125 applied in softmax.
// ---------------------------------------------------------------------------
#define FH_LD 72
#define FS_LD 68
#define FA_SMEM ((128 * FS_LD + 3 * 128) * 4 + \
                 (128 * FH_LD + 64 * FH_LD + 64 * FH_LD + 128 * FH_LD) * 2) // 91648

__global__ void __launch_bounds__(256)
flash_f16_kernel(const __half* __restrict__ qkv, __half* __restrict__ o)
{
    extern __shared__ char fsm[];
    float*  Ss    = (float*)fsm;                 // [128][FS_LD] fp32
    float*  row_m = Ss + 128 * FS_LD;
    float*  row_l = row_m + 128;
    float*  row_s = row_l + 128;
    __half* Qs    = (__half*)(row_s + 128);      // [128][FH_LD]
    __half* Ks    = Qs + 128 * FH_LD;            // [64][FH_LD]
    __half* Vt    = Ks + 64 * FH_LD;             // [64][FH_LD] (d-major)
    __half* Ps    = Vt + 64 * FH_LD;             // [128][FH_LD] fp16

    const uint32_t sbq = smem_u32(Qs);
    const uint32_t sbk = smem_u32(Ks);
    const int tid  = threadIdx.x;
    const int warp = tid >> 5;
    const int lane = tid & 31;
    const int fr = lane >> 2;            // 0..7
    const int fc = lane & 3;             // 0..3
    const int q0 = blockIdx.x * 128;
    const int b  = blockIdx.y / HH;
    const int h  = blockIdx.y % HH;
    const size_t headoff = (size_t)h * HD;

    if (tid < 128) { row_m[tid] = -INFINITY; row_l[tid] = 0.0f; }

    // Q tile: cp.async fp16 copy (128 rows x 8 x 16B)
    #pragma unroll
    for (int i = 0; i < 4; i++) {
        int idx = tid + i * 256;
        int r = idx >> 3, c8 = idx & 7;
        int n = q0 + r;
        int ns = n < NN ? n : NN - 1;
        const __half* src = qkv + (size_t)(b * NN + ns) * C3 + headoff + c8 * 8;
        cp_async16(sbq + (uint32_t)(r * FH_LD + c8 * 8) * 2u, src, n < NN ? 16u : 0u);
    }
    CP_COMMIT();

    float oacc[8][4];
    #pragma unroll
    for (int j = 0; j < 8; j++)
        #pragma unroll
        for (int e = 0; e < 4; e++) oacc[j][e] = 0.0f;

    const int ntiles = (NN + 63) / 64;   // 22

    for (int t = 0; t < ntiles; t++) {
        const int kv0 = t * 64;
        __syncthreads();                 // previous Ks/Vt/Ps readers done

        // K tile via cp.async (64 rows x 8 x 16B); V transposed manually
        #pragma unroll
        for (int i = 0; i < 2; i++) {
            int idx = tid + i * 256;
            int r = idx >> 3, c8 = idx & 7;
            int n = kv0 + r;
            int ns = n < NN ? n : NN - 1;
            const __half* src = qkv + (size_t)(b * NN + ns) * C3 + CC + headoff + c8 * 8;
            cp_async16(sbk + (uint32_t)(r * FH_LD + c8 * 8) * 2u, src, n < NN ? 16u : 0u);
        }
        CP_COMMIT();
        #pragma unroll
        for (int i = 0; i < 2; i++) {
            int idx = tid + i * 256;
            int r = idx >> 3, c8 = idx & 7;
            int n = kv0 + r;
            __half hv[8];
            if (n < NN) {
                *(uint4*)hv = *(const uint4*)(qkv + (size_t)(b * NN + n) * C3
                                              + 2 * CC + headoff + c8 * 8);
            } else {
                #pragma unroll
                for (int e2 = 0; e2 < 8; e2++) hv[e2] = __float2half(0.0f);
            }
            #pragma unroll
            for (int e2 = 0; e2 < 8; e2++)
                Vt[(c8 * 8 + e2) * FH_LD + r] = hv[e2];
        }
        CP_WAIT0();
        __syncthreads();

        // S = Q @ K^T : warp tile 16(q) x 64(kv); 4 k16 steps over d
        float sacc[8][4];
        #pragma unroll
        for (int j = 0; j < 8; j++)
            #pragma unroll
            for (int e = 0; e < 4; e++) sacc[j][e] = 0.0f;
        {
            const __half* ab = Qs + (warp * 16 + fr) * FH_LD + 2 * fc;
            const __half* bb = Ks + fr * FH_LD + 2 * fc;
            #pragma unroll
            for (int ks = 0; ks < 4; ks++) {
                uint32_t af[4], bf[2];
                const __half* pa = ab + ks * 16;
                af[0] = ldh2(pa);
                af[1] = ldh2(pa + 8 * FH_LD);
                af[2] = ldh2(pa + 8);
                af[3] = ldh2(pa + 8 * FH_LD + 8);
                #pragma unroll
                for (int j = 0; j < 8; j++) {
                    const __half* pb = bb + j * 8 * FH_LD + ks * 16;
                    bf[0] = ldh2(pb);
                    bf[1] = ldh2(pb + 8);
                    mma_f16(sacc[j], af, bf);
                }
            }
        }
        // write S (fp32)
        #pragma unroll
        for (int j = 0; j < 8; j++) {
            float* d0 = Ss + (warp * 16 + fr) * FS_LD + j * 8 + 2 * fc;
            d0[0] = sacc[j][0]; d0[1] = sacc[j][1];
            float* d1 = d0 + 8 * FS_LD;
            d1[0] = sacc[j][2]; d1[1] = sacc[j][3];
        }
        __syncthreads();

        // online softmax over 128 rows (two 64-row halves); scale here
        #pragma unroll
        for (int half = 0; half < 2; half++) {
            int r = (tid >> 2) + half * 64;
            int part = tid & 3;
            float pv[16];
            #pragma unroll
            for (int j4 = 0; j4 < 4; j4++) {
                float4 v4 = *(const float4*)&Ss[r * FS_LD + part * 16 + j4 * 4];
                pv[j4*4+0] = v4.x * 0.125f; pv[j4*4+1] = v4.y * 0.125f;
                pv[j4*4+2] = v4.z * 0.125f; pv[j4*4+3] = v4.w * 0.125f;
            }
            if (kv0 + 64 > NN) {
                #pragma unroll
                for (int j = 0; j < 16; j++)
                    if (kv0 + part * 16 + j >= NN) pv[j] = -INFINITY;
            }
            float lmax = pv[0];
            #pragma unroll
            for (int j = 1; j < 16; j++) lmax = fmaxf(lmax, pv[j]);
            lmax = fmaxf(lmax, __shfl_xor_sync(0xffffffffu, lmax, 1));
            lmax = fmaxf(lmax, __shfl_xor_sync(0xffffffffu, lmax, 2));
            float m_old = row_m[r];
            float m_new = fmaxf(m_old, lmax);
            float lsum = 0.0f;
            #pragma unroll
            for (int j = 0; j < 16; j++) {
                pv[j] = __expf(pv[j] - m_new);
                lsum += pv[j];
            }
            lsum += __shfl_xor_sync(0xffffffffu, lsum, 1);
            lsum += __shfl_xor_sync(0xffffffffu, lsum, 2);
            float sc = __expf(m_old - m_new);
            if (part == 0) {
                row_s[r] = sc;
                row_m[r] = m_new;
                row_l[r] = row_l[r] * sc + lsum;
            }
            #pragma unroll
            for (int j4 = 0; j4 < 4; j4++) {
                *(__half2*)&Ps[r * FH_LD + part * 16 + j4 * 4] =
                    __floats2half2_rn(pv[j4 * 4 + 0], pv[j4 * 4 + 1]);
                *(__half2*)&Ps[r * FH_LD + part * 16 + j4 * 4 + 2] =
                    __floats2half2_rn(pv[j4 * 4 + 2], pv[j4 * 4 + 3]);
            }
        }
        __syncthreads();

        // rescale O and accumulate P @ V : warp tile 16(q) x 64(d), k over kv
        {
            float rs0 = row_s[warp * 16 + fr];
            float rs1 = row_s[warp * 16 + fr + 8];
            #pragma unroll
            for (int j = 0; j < 8; j++) {
                oacc[j][0] *= rs0; oacc[j][1] *= rs0;
                oacc[j][2] *= rs1; oacc[j][3] *= rs1;
            }
            const __half* ap = Ps + (warp * 16 + fr) * FH_LD + 2 * fc;
            const __half* bp = Vt + fr * FH_LD + 2 * fc;
            #pragma unroll
            for (int ks = 0; ks < 4; ks++) {
                uint32_t af[4], bf[2];
                const __half* pa = ap + ks * 16;
                af[0] = ldh2(pa);
                af[1] = ldh2(pa + 8 * FH_LD);
                af[2] = ldh2(pa + 8);
                af[3] = ldh2(pa + 8 * FH_LD + 8);
                #pragma unroll
                for (int j = 0; j < 8; j++) {
                    const __half* pb = bp + j * 8 * FH_LD + ks * 16;
                    bf[0] = ldh2(pb);
                    bf[1] = ldh2(pb + 8);
                    mma_f16(oacc[j], af, bf);
                }
            }
        }
    }

    // normalize + store fp16
    {
        int r0 = warp * 16 + fr;
        float inv0 = 1.0f / row_l[r0];
        float inv1 = 1.0f / row_l[r0 + 8];
        int n0g = q0 + r0;
        int n1g = n0g + 8;
        #pragma unroll
        for (int j = 0; j < 8; j++) {
            size_t col = headoff + j * 8 + 2 * fc;
            if (n0g < NN) {
                *(__half2*)&o[(size_t)(b * NN + n0g) * CC + col] =
                    __floats2half2_rn(oacc[j][0] * inv0, oacc[j][1] * inv0);
            }
            if (n1g < NN) {
                *(__half2*)&o[(size_t)(b * NN + n1g) * CC + col] =
                    __floats2half2_rn(oacc[j][2] * inv1, oacc[j][3] * inv1);
            }
        }
    }
}

// ---------------------------------------------------------------------------
// Launch
// ---------------------------------------------------------------------------
static inline void conv_h(const float* in, __half* out, int elems) {
    int n4 = elems / 4;
    f2h_kernel<<<(n4 + 255) / 256, 256>>>(in, out, n4);
}

extern "C" void kernel_launch(void* const* d_in, const int* in_sizes, int n_in,
                              void* d_out, int out_size)
{
    const float* x      = (const float*)d_in[0];
    const float* freqs  = (const float*)d_in[1];
    const float* ln1_g  = (const float*)d_in[2];
    const float* ln1_b  = (const float*)d_in[3];
    const float* qkv_w  = (const float*)d_in[4];
    const float* qkv_b  = (const float*)d_in[5];
    const float* proj_w = (const float*)d_in[6];
    const float* proj_b = (const float*)d_in[7];
    const float* ln2_g  = (const float*)d_in[8];
    const float* ln2_b  = (const float*)d_in[9];
    const float* w1     = (const float*)d_in[10];
    const float* b1     = (const float*)d_in[11];
    const float* w2     = (const float*)d_in[12];
    const float* b2     = (const float*)d_in[13];
    const float* w3     = (const float*)d_in[14];
    const float* b3     = (const float*)d_in[15];
    float* out = (float*)d_out;

    __half *h_buf, *qkv_buf, *attn_buf, *x1_buf, *hid_buf, *wh;
    cudaGetSymbolAddress((void**)&h_buf, g_h);
    cudaGetSymbolAddress((void**)&qkv_buf, g_qkv);
    cudaGetSymbolAddress((void**)&attn_buf, g_attn);
    cudaGetSymbolAddress((void**)&x1_buf, g_x1);
    cudaGetSymbolAddress((void**)&hid_buf, g_hid);
    cudaGetSymbolAddress((void**)&wh, g_wh);

    cudaFuncSetAttribute(gemm_f16<0>,
                         cudaFuncAttributeMaxDynamicSharedMemorySize, HG_SMEM);
    cudaFuncSetAttribute(gemm_f16<1>,
                         cudaFuncAttributeMaxDynamicSharedMemorySize, HG_SMEM);
    cudaFuncSetAttribute(gemm_f16<2>,
                         cudaFuncAttributeMaxDynamicSharedMemorySize, HG_SMEM);
    cudaFuncSetAttribute(gemm_f16<3>,
                         cudaFuncAttributeMaxDynamicSharedMemorySize, HG_SMEM);
    cudaFuncSetAttribute(flash_f16_kernel,
                         cudaFuncAttributeMaxDynamicSharedMemorySize, FA_SMEM);

    const int mblocks = (MM + 127) / 128;   // 86

    // 0) weights -> fp16
    conv_h(qkv_w,  wh + WH_QKV,  C3 * CC);
    conv_h(proj_w, wh + WH_PROJ, CC * CC);
    conv_h(w1,     wh + WH_W1,   HID * CC);
    conv_h(w2,     wh + WH_W2,   HID * CC);
    conv_h(w3,     wh + WH_W3,   CC * HID);

    // 1) LN1 -> fp16
    ln_kernel<<<MM, 256>>>(x, ln1_g, ln1_b, h_buf);

    // 2) QKV GEMM -> fp16
    gemm_f16<3><<<dim3(C3 / 128, mblocks), 256, HG_SMEM>>>(
        h_buf, wh + WH_QKV, qkv_b, nullptr, qkv_buf, MM, C3, CC);

    // 3) RoPE in place (fp16)
    rope_kernel<<<MM, 256>>>(qkv_buf, freqs);

    // 4) Flash attention (BQ=128) -> fp16
    {
        dim3 grid((NN + 127) / 128, BB * HH);   // (11, 96)
        flash_f16_kernel<<<grid, 256, FA_SMEM>>>(qkv_buf, attn_buf);
    }

    // 5) proj GEMM + residual(x) -> out (fp32)
    gemm_f16<1><<<dim3(CC / 128, mblocks), 256, HG_SMEM>>>(
        attn_buf, wh + WH_PROJ, proj_b, x, out, MM, CC, CC);

    // 6) LN2 -> fp16
    ln_kernel<<<MM, 256>>>(out, ln2_g, ln2_b, h_buf);

    // 7) x1 GEMM -> fp16
    gemm_f16<3><<<dim3(HID / 128, mblocks), 256, HG_SMEM>>>(
        h_buf, wh + WH_W1, b1, nullptr, x1_buf, MM, HID, CC);

    // 8) x2 GEMM with fused SwiGLU (reads fp16 x1) -> hid (fp16)
    gemm_f16<2><<<dim3(HID / 128, mblocks), 256, HG_SMEM>>>(
        h_buf, wh + WH_W2, b2, x1_buf, hid_buf, MM, HID, CC);

    // 9) mlp GEMM + residual -> out (fp32)
    gemm_f16<1><<<dim3(CC / 128, mblocks), 256, HG_SMEM>>>(
        hid_buf, wh + WH_W3, b3, out, out, MM, CC, HID);
}